// round 16
// baseline (speedup 1.0000x reference)
#include <cuda_runtime.h>
#include <cstdint>
#include <math.h>

// ---------------------------------------------------------------------------
// EZLSTM on GB300 (sm_103a) — persistent kernel, tf32-bit h, cp.async pipeline.
// R15: exact 4821us baseline (R11 source) + STRIPED grid barrier:
//      8 counters 128B apart, 16 CTAs arrive per counter (16-way contention
//      instead of 128-way; contended L2-atomic drain ~27cyc/op -> ~3.5k cyc
//      per step on one address). Poller sums 8 acquire-loads.
//      Safety: a CTA arrives for step t+1 only after passing barrier t, so
//      sum >= 128(t+1) iff every CTA arrived; per-location release/acquire
//      orders each CTA's h stores before the poller's observation.
//
//   128 CTAs (1/SM), 512 steps in ONE launch.
//   CTA owns 8 hidden cols x 4 gates (N=32), all 64 batch rows, K=1024.
//   U weights in SMEM (tf32, mma-fragment order) for the whole kernel.
//   h in GLOBAL as tf32 bits (converted once by producer), double buffered.
//   h chunks stream global->smem via cp.async, 4-stage ring, 2 chunks ahead.
// ---------------------------------------------------------------------------

#define B_SZ 64
#define T_SZ 512
#define D_SZ 1024
#define H_SZ 1024

#define GRID    128            // 1 CTA/SM, all co-resident
#define NTHR    256            // 8 warps
#define KCH     64             // K per pipeline stage
#define NCH     (H_SZ / KCH)   // 16 chunks
#define NSTG    4              // pipeline stages
#define A_STR   68             // % 32 == 4 -> conflict-free (4r+kq) pattern
#define A_STAGE (64 * A_STR)   // 4352 words per stage
#define NBARS   8              // barrier stripes

// smem layout (32-bit words)
#define OFF_W   0                        // 32768 : U fragments (tf32 bits)
#define OFF_A   32768                    // 4 * 4352 = 17408 : h stage ring
#define OFF_Z   (OFF_A + NSTG * A_STAGE) // 50176 : z staging (64*33 = 2112)
#define OFF_G   (OFF_Z + 2112)           // 52288 : input-gate cache (2048)
#define OFF_C   (OFF_G + 2048)           // 54336 : cell state (512)
#define SMEM_WORDS (OFF_C + 512)         // 54848
#define SMEM_BYTES (SMEM_WORDS * 4)      // 219392 B <= 227 KB

// persistent scratch
__device__ uint32_t g_h[2][B_SZ * H_SZ];     // h as tf32 bit patterns
__device__ float    g_gates[4 * B_SZ * H_SZ];
__device__ unsigned g_bars[NBARS * 32];      // striped counters, 128B apart

__device__ __forceinline__ uint32_t f2tf32(float f) {
    uint32_t r;
    asm("cvt.rna.tf32.f32 %0, %1;" : "=r"(r) : "f"(f));
    return r;
}
__device__ __forceinline__ void stcg_u32(uint32_t* p, uint32_t v) {
    asm volatile("st.global.cg.u32 [%0], %1;" :: "l"(p), "r"(v));
}
__device__ __forceinline__ void cp_async16(uint32_t smem_addr, const void* gptr) {
    asm volatile("cp.async.cg.shared.global [%0], [%1], 16;"
                 :: "r"(smem_addr), "l"(gptr));
}
__device__ __forceinline__ void cp_commit() {
    asm volatile("cp.async.commit_group;");
}
template <int N>
__device__ __forceinline__ void cp_wait() {
    asm volatile("cp.async.wait_group %0;" :: "n"(N));
}
__device__ __forceinline__ unsigned ld_acq(const unsigned* p) {
    unsigned v;
    asm volatile("ld.acquire.gpu.global.u32 %0, [%1];"
                 : "=r"(v) : "l"(p) : "memory");
    return v;
}
// branch-free sigmoid: ex2/rcp approx err ~1e-7 abs << tf32 noise (~1e-4).
__device__ __forceinline__ float fast_sigmoid(float x) {
    float e, r;
    asm("ex2.approx.ftz.f32 %0, %1;" : "=f"(e) : "f"(-1.44269504088896f * x));
    asm("rcp.approx.ftz.f32 %0, %1;" : "=f"(r) : "f"(1.0f + e));
    return r;
}
__device__ __forceinline__ float fast_tanh(float x) {
    return fmaf(2.0f, fast_sigmoid(2.0f * x), -1.0f);
}

// ---------------------------------------------------------------------------
// Fused: zero h/barriers + g[gate] = x0 @ W_gate + b_gate (one-time, fp32).
__global__ void lstm_init_gates(const float* __restrict__ x,
    const float* __restrict__ wf, const float* __restrict__ wi,
    const float* __restrict__ wo, const float* __restrict__ wc,
    const float* __restrict__ bf, const float* __restrict__ bi,
    const float* __restrict__ bo, const float* __restrict__ bc)
{
    {
        const int lb  = blockIdx.x + 4 * (blockIdx.y + 8 * blockIdx.z);
        const int gid = lb * blockDim.x + threadIdx.x;       // 0..32767
        g_h[0][gid]         = 0u;                            // tf32 bits of 0
        g_h[0][gid + 32768] = 0u;
        if (gid < NBARS * 32) g_bars[gid] = 0u;
    }

    const int gate = blockIdx.z;
    const int bg = blockIdx.y;
    const int j = blockIdx.x * blockDim.x + threadIdx.x;
    const float* w  = (gate == 0) ? wf : (gate == 1) ? wi : (gate == 2) ? wo : wc;
    const float* bb = (gate == 0) ? bf : (gate == 1) ? bi : (gate == 2) ? bo : bc;

    float acc[8];
    #pragma unroll
    for (int r = 0; r < 8; ++r) acc[r] = bb[j];
    for (int d = 0; d < D_SZ; ++d) {
        const float wv = w[d * H_SZ + j];
        #pragma unroll
        for (int r = 0; r < 8; ++r)
            acc[r] = fmaf(x[(bg * 8 + r) * (T_SZ * D_SZ) + d], wv, acc[r]);
    }
    #pragma unroll
    for (int r = 0; r < 8; ++r)
        g_gates[gate * (B_SZ * H_SZ) + (bg * 8 + r) * H_SZ + j] = acc[r];
}

// ---------------------------------------------------------------------------
__global__ void __launch_bounds__(NTHR, 1) lstm_persistent(
    const float* __restrict__ uf, const float* __restrict__ ui,
    const float* __restrict__ uo, const float* __restrict__ uc,
    float* __restrict__ out)
{
    extern __shared__ uint32_t sm[];
    uint32_t* sW = sm + OFF_W;
    uint32_t* sA = sm + OFF_A;
    float*    sZ = reinterpret_cast<float*>(sm + OFF_Z);
    float*    sG = reinterpret_cast<float*>(sm + OFF_G);
    float*    sC = reinterpret_cast<float*>(sm + OFF_C);

    const int tid  = threadIdx.x;
    const int lane = tid & 31;
    const int wrp  = tid >> 5;
    const int mt   = wrp & 3;        // m16 tile (rows mt*16..+15)
    const int np   = wrp >> 2;       // n-pair: ntiles {2np, 2np+1}
    const int j0   = blockIdx.x * 8; // this CTA's 8 hidden columns
    const int bstripe = (blockIdx.x & (NBARS - 1)) << 5;  // arrival counter

    const uint32_t sA_base = (uint32_t)__cvta_generic_to_shared(sA);

    // ---- one-time: pack U into SMEM, mma-B-fragment order, tf32 bits.
    #pragma unroll
    for (int gate = 0; gate < 4; ++gate) {
        const float* u = (gate == 0) ? uf : (gate == 1) ? ui
                       : (gate == 2) ? uo : uc;
        for (int idx = tid; idx < 8192; idx += NTHR) {
            const int k = idx >> 3, j = idx & 7;
            const float v = u[k * H_SZ + j0 + j];
            const int s = k >> 3, c = k & 7, half = c >> 2, kq = c & 3;
            const int l = j * 4 + kq;
            sW[((((s * 4 + gate) * 32) + l) << 1) + half] = f2tf32(v);
        }
    }
    for (int idx = tid; idx < 2048; idx += NTHR) {
        const int gate = idx >> 9, rem = idx & 511;
        const int b = rem >> 3, j = rem & 7;
        sG[idx] = g_gates[gate * (B_SZ * H_SZ) + b * H_SZ + j0 + j];
    }
    for (int idx = tid; idx < 512; idx += NTHR) sC[idx] = 0.0f;
    __syncthreads();

    const int r  = lane >> 2;        // mma row-in-tile
    const int kq = lane & 3;         // mma k-quad
    const int cq = (lane & 3) * 2;   // mma col pair in accumulator layout

    // ---- 512 recurrent steps
    for (int t = 0; t < T_SZ; ++t) {
        const uint32_t* __restrict__ hsrc = g_h[t & 1];
        uint32_t* __restrict__ hdst = g_h[(t + 1) & 1];

        float acc[2][4];
        #pragma unroll
        for (int n = 0; n < 2; ++n)
            #pragma unroll
            for (int q = 0; q < 4; ++q) acc[n][q] = 0.0f;

        // issue chunk kc into ring stage kc&3 (4 x 16B cp.async per thread)
        auto issue = [&](int kc) {
            const int stg = kc & (NSTG - 1);
            #pragma unroll
            for (int q = 0; q < 4; ++q) {
                const int f = tid + NTHR * q;          // 0..1023
                const int row = f >> 4;                // 0..63
                const int col = (f & 15) << 2;         // 0..60 step 4
                cp_async16(sA_base + (stg * A_STAGE + row * A_STR + col) * 4,
                           hsrc + row * H_SZ + kc * KCH + col);
            }
            cp_commit();
        };

        issue(0);
        issue(1);

        #pragma unroll
        for (int kc = 0; kc < NCH; ++kc) {
            // keep 2 chunks in flight
            if (kc + 2 < NCH) { issue(kc + 2); cp_wait<2>(); }
            else if (kc + 1 < NCH) { cp_wait<1>(); }
            else { cp_wait<0>(); }
            __syncthreads();

            // compute chunk kc from its ring stage
            const uint32_t* A = sA + (kc & (NSTG - 1)) * A_STAGE;
            #pragma unroll
            for (int s = 0; s < KCH / 8; ++s) {
                const int k0 = s * 8;
                const uint32_t a0 = A[(mt * 16 + r)     * A_STR + k0 + kq];
                const uint32_t a1 = A[(mt * 16 + r + 8) * A_STR + k0 + kq];
                const uint32_t a2 = A[(mt * 16 + r)     * A_STR + k0 + kq + 4];
                const uint32_t a3 = A[(mt * 16 + r + 8) * A_STR + k0 + kq + 4];
                const int sg = kc * (KCH / 8) + s;
                #pragma unroll
                for (int n = 0; n < 2; ++n) {
                    const int nt = np * 2 + n;
                    const uint2 bv = *reinterpret_cast<const uint2*>(
                        &sW[(((sg * 4 + nt) * 32) + lane) << 1]);
                    asm volatile(
                        "mma.sync.aligned.m16n8k8.row.col.f32.tf32.tf32.f32 "
                        "{%0,%1,%2,%3},{%4,%5,%6,%7},{%8,%9},{%0,%1,%2,%3};\n"
                        : "+f"(acc[n][0]), "+f"(acc[n][1]),
                          "+f"(acc[n][2]), "+f"(acc[n][3])
                        : "r"(a0), "r"(a1), "r"(a2), "r"(a3),
                          "r"(bv.x), "r"(bv.y));
                }
            }
        }

        // ---- stage z (64 rows x 32 logical cols) into smem
        {
            #pragma unroll
            for (int n = 0; n < 2; ++n) {
                const int ncol = (np * 2 + n) * 8 + cq;
                const int rr = mt * 16 + r;
                sZ[rr * 33 + ncol]           = acc[n][0];
                sZ[rr * 33 + ncol + 1]       = acc[n][1];
                sZ[(rr + 8) * 33 + ncol]     = acc[n][2];
                sZ[(rr + 8) * 33 + ncol + 1] = acc[n][3];
            }
        }
        __syncthreads();

        // ---- gate math + state update: 512 outputs / 256 threads
        #pragma unroll
        for (int e = 0; e < 2; ++e) {
            const int flat = tid + NTHR * e;       // = b*8 + j
            const int b = flat >> 3, j = flat & 7;
            const float zf = sZ[b * 33 + j]      + sG[flat];
            const float zi = sZ[b * 33 + 8 + j]  + sG[512 + flat];
            const float zo = sZ[b * 33 + 16 + j] + sG[1024 + flat];
            const float zc = sZ[b * 33 + 24 + j] + sG[1536 + flat];
            const float fg = fast_sigmoid(zf);
            const float ig = fast_sigmoid(zi);
            const float og = fast_sigmoid(zo);
            const float ch = fast_tanh(zc);
            const float cn = fg * sC[flat] + ig * ch;
            const float hn = og * fast_tanh(cn);
            sC[flat] = cn;
            stcg_u32(&hdst[b * H_SZ + j0 + j], f2tf32(hn));  // converted ONCE
            out[(b * T_SZ + t) * H_SZ + j0 + j] = hn;
        }

        // ---- striped grid barrier: release-arrive on this CTA's stripe,
        //      poller sums all stripes with acquire loads.
        __syncthreads();            // all h stores issued before the arrive
        if (tid == 0) {
            asm volatile("red.release.gpu.global.add.u32 [%0], %1;"
                         :: "l"(&g_bars[bstripe]), "r"(1u) : "memory");
            const unsigned target = (unsigned)(t + 1) * GRID;
            unsigned s;
            do {
                s = 0;
                #pragma unroll
                for (int i = 0; i < NBARS; ++i)
                    s += ld_acq(&g_bars[i << 5]);
            } while (s < target);
        }
        __syncthreads();
    }
}

// ---------------------------------------------------------------------------
extern "C" void kernel_launch(void* const* d_in, const int* in_sizes, int n_in,
                              void* d_out, int out_size) {
    (void)in_sizes; (void)n_in; (void)out_size;
    const float* x  = (const float*)d_in[0];
    const float* wf = (const float*)d_in[1];
    const float* wi = (const float*)d_in[2];
    const float* wo = (const float*)d_in[3];
    const float* wc = (const float*)d_in[4];
    const float* uf = (const float*)d_in[5];
    const float* ui = (const float*)d_in[6];
    const float* uo = (const float*)d_in[7];
    const float* uc = (const float*)d_in[8];
    const float* bf = (const float*)d_in[9];
    const float* bi = (const float*)d_in[10];
    const float* bo = (const float*)d_in[11];
    const float* bc = (const float*)d_in[12];
    float* out = (float*)d_out;

    cudaFuncSetAttribute(lstm_persistent,
                         cudaFuncAttributeMaxDynamicSharedMemorySize, SMEM_BYTES);

    lstm_init_gates<<<dim3(H_SZ / 256, B_SZ / 8, 4), 256>>>(
        x, wf, wi, wo, wc, bf, bi, bo, bc);
    lstm_persistent<<<GRID, NTHR, SMEM_BYTES>>>(uf, ui, uo, uc, out);
}

// round 17
// speedup vs baseline: 1.5322x; 1.5322x over previous
#include <cuda_runtime.h>
#include <cstdint>
#include <math.h>

// ---------------------------------------------------------------------------
// EZLSTM on GB300 (sm_103a) — persistent kernel, tf32-bit h, cp.async pipeline.
// R16 = R11 base (4821us: single-counter barrier, fast epilogue, 4-stage
// cp.async) + MINIMAL-DUPLICATION warp grid: 8-way K-split, each warp owns
// the full m64 x n32 tile for one k8-group per chunk -> A and B fragments
// cross the smem crossbar exactly ONCE (was A x2, B x4). Per-warp partials
// staged in smem (stride 40: conflict-free + 8B-aligned) overlaying the idle
// stage ring, reduced in the epilogue.
// ---------------------------------------------------------------------------

#define B_SZ 64
#define T_SZ 512
#define D_SZ 1024
#define H_SZ 1024

#define GRID    128            // 1 CTA/SM, all co-resident
#define NTHR    256            // 8 warps
#define KCH     64             // K per pipeline stage
#define NCH     (H_SZ / KCH)   // 16 chunks
#define NSTG    4              // pipeline stages
#define A_STR   68             // % 32 == 4 -> conflict-free (4r+kq) pattern
#define A_STAGE (64 * A_STR)   // 4352 words per stage
#define Z_STR   40             // bank-perfect (8r mod 32 spread) + even
#define Z_WARP  (64 * Z_STR)   // 2560 words per warp partial

// smem layout (32-bit words). sZ overlays the stage ring (idle from the
// post-mainloop sync until next step's issue(0), fenced by the grid barrier)
// and extends past it; sG/sC sit beyond the Z region.
#define OFF_W   0                        // 32768 : U fragments (tf32 bits)
#define OFF_A   32768                    // ring 4*4352 = 17408
#define OFF_Z   OFF_A                    // 8*2560 = 20480 (overlay + spill)
#define OFF_G   (OFF_A + 8 * Z_WARP)     // 53248 : input-gate cache (2048)
#define OFF_C   (OFF_G + 2048)           // 55296 : cell state (512)
#define SMEM_WORDS (OFF_C + 512)         // 55808
#define SMEM_BYTES (SMEM_WORDS * 4)      // 223232 B

// persistent scratch
__device__ uint32_t g_h[2][B_SZ * H_SZ];     // h as tf32 bit patterns
__device__ float    g_gates[4 * B_SZ * H_SZ];
__device__ unsigned g_bar;

__device__ __forceinline__ uint32_t f2tf32(float f) {
    uint32_t r;
    asm("cvt.rna.tf32.f32 %0, %1;" : "=r"(r) : "f"(f));
    return r;
}
__device__ __forceinline__ void stcg_u32(uint32_t* p, uint32_t v) {
    asm volatile("st.global.cg.u32 [%0], %1;" :: "l"(p), "r"(v));
}
__device__ __forceinline__ void cp_async16(uint32_t smem_addr, const void* gptr) {
    asm volatile("cp.async.cg.shared.global [%0], [%1], 16;"
                 :: "r"(smem_addr), "l"(gptr));
}
__device__ __forceinline__ void cp_commit() {
    asm volatile("cp.async.commit_group;");
}
template <int N>
__device__ __forceinline__ void cp_wait() {
    asm volatile("cp.async.wait_group %0;" :: "n"(N));
}
// branch-free sigmoid: ex2/rcp approx err ~1e-7 abs << tf32 noise (~1e-4).
__device__ __forceinline__ float fast_sigmoid(float x) {
    float e, r;
    asm("ex2.approx.ftz.f32 %0, %1;" : "=f"(e) : "f"(-1.44269504088896f * x));
    asm("rcp.approx.ftz.f32 %0, %1;" : "=f"(r) : "f"(1.0f + e));
    return r;
}
__device__ __forceinline__ float fast_tanh(float x) {
    return fmaf(2.0f, fast_sigmoid(2.0f * x), -1.0f);
}

// ---------------------------------------------------------------------------
// Fused: zero h/barrier + g[gate] = x0 @ W_gate + b_gate (one-time, fp32).
__global__ void lstm_init_gates(const float* __restrict__ x,
    const float* __restrict__ wf, const float* __restrict__ wi,
    const float* __restrict__ wo, const float* __restrict__ wc,
    const float* __restrict__ bf, const float* __restrict__ bi,
    const float* __restrict__ bo, const float* __restrict__ bc)
{
    {
        const int lb  = blockIdx.x + 4 * (blockIdx.y + 8 * blockIdx.z);
        const int gid = lb * blockDim.x + threadIdx.x;       // 0..32767
        g_h[0][gid]         = 0u;                            // tf32 bits of 0
        g_h[0][gid + 32768] = 0u;
        if (gid == 0) g_bar = 0u;
    }

    const int gate = blockIdx.z;
    const int bg = blockIdx.y;
    const int j = blockIdx.x * blockDim.x + threadIdx.x;
    const float* w  = (gate == 0) ? wf : (gate == 1) ? wi : (gate == 2) ? wo : wc;
    const float* bb = (gate == 0) ? bf : (gate == 1) ? bi : (gate == 2) ? bo : bc;

    float acc[8];
    #pragma unroll
    for (int r = 0; r < 8; ++r) acc[r] = bb[j];
    for (int d = 0; d < D_SZ; ++d) {
        const float wv = w[d * H_SZ + j];
        #pragma unroll
        for (int r = 0; r < 8; ++r)
            acc[r] = fmaf(x[(bg * 8 + r) * (T_SZ * D_SZ) + d], wv, acc[r]);
    }
    #pragma unroll
    for (int r = 0; r < 8; ++r)
        g_gates[gate * (B_SZ * H_SZ) + (bg * 8 + r) * H_SZ + j] = acc[r];
}

// ---------------------------------------------------------------------------
__global__ void __launch_bounds__(NTHR) lstm_persistent(
    const float* __restrict__ uf, const float* __restrict__ ui,
    const float* __restrict__ uo, const float* __restrict__ uc,
    float* __restrict__ out)
{
    extern __shared__ uint32_t sm[];
    uint32_t* sW = sm + OFF_W;
    uint32_t* sA = sm + OFF_A;
    float*    sZ = reinterpret_cast<float*>(sm + OFF_Z);   // overlays ring
    float*    sG = reinterpret_cast<float*>(sm + OFF_G);
    float*    sC = reinterpret_cast<float*>(sm + OFF_C);

    const int tid  = threadIdx.x;
    const int lane = tid & 31;
    const int wrp  = tid >> 5;       // this warp's k8-group within each chunk
    const int j0   = blockIdx.x * 8; // this CTA's 8 hidden columns

    const uint32_t sA_base = (uint32_t)__cvta_generic_to_shared(sA);

    // ---- one-time: pack U into SMEM, mma-B-fragment order, tf32 bits.
    #pragma unroll
    for (int gate = 0; gate < 4; ++gate) {
        const float* u = (gate == 0) ? uf : (gate == 1) ? ui
                       : (gate == 2) ? uo : uc;
        for (int idx = tid; idx < 8192; idx += NTHR) {
            const int k = idx >> 3, j = idx & 7;
            const float v = u[k * H_SZ + j0 + j];
            const int s = k >> 3, c = k & 7, half = c >> 2, kq = c & 3;
            const int l = j * 4 + kq;
            sW[((((s * 4 + gate) * 32) + l) << 1) + half] = f2tf32(v);
        }
    }
    for (int idx = tid; idx < 2048; idx += NTHR) {
        const int gate = idx >> 9, rem = idx & 511;
        const int b = rem >> 3, j = rem & 7;
        sG[idx] = g_gates[gate * (B_SZ * H_SZ) + b * H_SZ + j0 + j];
    }
    for (int idx = tid; idx < 512; idx += NTHR) sC[idx] = 0.0f;
    __syncthreads();

    const int r  = lane >> 2;        // mma row-in-tile
    const int kq = lane & 3;         // mma k-quad
    const int cq = (lane & 3) * 2;   // mma col pair in accumulator layout
    const int k0 = wrp * 8;          // this warp's k8-group offset in a chunk

    // ---- 512 recurrent steps
    for (int t = 0; t < T_SZ; ++t) {
        const uint32_t* __restrict__ hsrc = g_h[t & 1];
        uint32_t* __restrict__ hdst = g_h[(t + 1) & 1];

        float acc[4][4][4];          // [mt][nt][q]: full m64n32, k-partial
        #pragma unroll
        for (int m = 0; m < 4; ++m)
            #pragma unroll
            for (int n = 0; n < 4; ++n)
                #pragma unroll
                for (int q = 0; q < 4; ++q) acc[m][n][q] = 0.0f;

        // issue chunk kc into ring stage kc&3 (4 x 16B cp.async per thread)
        auto issue = [&](int kc) {
            const int stg = kc & (NSTG - 1);
            #pragma unroll
            for (int q = 0; q < 4; ++q) {
                const int f = tid + NTHR * q;          // 0..1023
                const int row = f >> 4;                // 0..63
                const int col = (f & 15) << 2;         // 0..60 step 4
                cp_async16(sA_base + (stg * A_STAGE + row * A_STR + col) * 4,
                           hsrc + row * H_SZ + kc * KCH + col);
            }
            cp_commit();
        };

        issue(0);
        issue(1);

        #pragma unroll
        for (int kc = 0; kc < NCH; ++kc) {
            if (kc + 2 < NCH) { issue(kc + 2); cp_wait<2>(); }
            else if (kc + 1 < NCH) { cp_wait<1>(); }
            else { cp_wait<0>(); }
            __syncthreads();

            // this warp's k8-group of chunk kc: A x1, B x1 across the CTA
            const uint32_t* A = sA + (kc & (NSTG - 1)) * A_STAGE;
            uint32_t af[4][4];
            #pragma unroll
            for (int mt = 0; mt < 4; ++mt) {
                af[mt][0] = A[(mt * 16 + r)     * A_STR + k0 + kq];
                af[mt][1] = A[(mt * 16 + r + 8) * A_STR + k0 + kq];
                af[mt][2] = A[(mt * 16 + r)     * A_STR + k0 + kq + 4];
                af[mt][3] = A[(mt * 16 + r + 8) * A_STR + k0 + kq + 4];
            }
            const int sg = kc * 8 + wrp;
            uint2 bv[4];
            #pragma unroll
            for (int nt = 0; nt < 4; ++nt)
                bv[nt] = *reinterpret_cast<const uint2*>(
                    &sW[(((sg * 4 + nt) * 32) + lane) << 1]);
            #pragma unroll
            for (int mt = 0; mt < 4; ++mt)
                #pragma unroll
                for (int nt = 0; nt < 4; ++nt) {
                    asm volatile(
                        "mma.sync.aligned.m16n8k8.row.col.f32.tf32.tf32.f32 "
                        "{%0,%1,%2,%3},{%4,%5,%6,%7},{%8,%9},{%0,%1,%2,%3};\n"
                        : "+f"(acc[mt][nt][0]), "+f"(acc[mt][nt][1]),
                          "+f"(acc[mt][nt][2]), "+f"(acc[mt][nt][3])
                        : "r"(af[mt][0]), "r"(af[mt][1]),
                          "r"(af[mt][2]), "r"(af[mt][3]),
                          "r"(bv[nt].x), "r"(bv[nt].y));
                }
        }
        __syncthreads();   // ring reads done everywhere -> sZ overlay safe

        // ---- stage this warp's m64n32 k-partial (stride 40: bank-perfect,
        //      even -> 8B-aligned float2)
        {
            float* Zw = sZ + wrp * Z_WARP;
            #pragma unroll
            for (int mt = 0; mt < 4; ++mt)
                #pragma unroll
                for (int nt = 0; nt < 4; ++nt) {
                    const int rr = mt * 16 + r;
                    const int ncol = nt * 8 + cq;
                    *reinterpret_cast<float2*>(&Zw[rr * Z_STR + ncol]) =
                        make_float2(acc[mt][nt][0], acc[mt][nt][1]);
                    *reinterpret_cast<float2*>(&Zw[(rr + 8) * Z_STR + ncol]) =
                        make_float2(acc[mt][nt][2], acc[mt][nt][3]);
                }
        }
        __syncthreads();

        // ---- reduce 8 k-partials + gate math + state: 512 out / 256 thr
        #pragma unroll
        for (int e = 0; e < 2; ++e) {
            const int flat = tid + NTHR * e;       // = b*8 + j
            const int b = flat >> 3, j = flat & 7;
            float z[4];
            #pragma unroll
            for (int g = 0; g < 4; ++g) {
                float s = sG[g * 512 + flat];
                #pragma unroll
                for (int w = 0; w < 8; ++w)
                    s += sZ[w * Z_WARP + b * Z_STR + g * 8 + j];
                z[g] = s;
            }
            const float fg = fast_sigmoid(z[0]);
            const float ig = fast_sigmoid(z[1]);
            const float og = fast_sigmoid(z[2]);
            const float ch = fast_tanh(z[3]);
            const float cn = fg * sC[flat] + ig * ch;
            const float hn = og * fast_tanh(cn);
            sC[flat] = cn;
            stcg_u32(&hdst[b * H_SZ + j0 + j], f2tf32(hn));  // converted ONCE
            out[(b * T_SZ + t) * H_SZ + j0 + j] = hn;
        }

        // ---- grid barrier: single counter (R15 stripe regressed; final)
        __syncthreads();            // all h stores issued before the arrive
        if (tid == 0) {
            asm volatile("red.release.gpu.global.add.u32 [%0], %1;"
                         :: "l"(&g_bar), "r"(1u) : "memory");
            const unsigned target = (unsigned)(t + 1) * GRID;
            unsigned v;
            do {
                asm volatile("ld.acquire.gpu.global.u32 %0, [%1];"
                             : "=r"(v) : "l"(&g_bar) : "memory");
            } while (v < target);
        }
        __syncthreads();            // also fences sZ overlay vs next issue(0)
    }
}

// ---------------------------------------------------------------------------
extern "C" void kernel_launch(void* const* d_in, const int* in_sizes, int n_in,
                              void* d_out, int out_size) {
    (void)in_sizes; (void)n_in; (void)out_size;
    const float* x  = (const float*)d_in[0];
    const float* wf = (const float*)d_in[1];
    const float* wi = (const float*)d_in[2];
    const float* wo = (const float*)d_in[3];
    const float* wc = (const float*)d_in[4];
    const float* uf = (const float*)d_in[5];
    const float* ui = (const float*)d_in[6];
    const float* uo = (const float*)d_in[7];
    const float* uc = (const float*)d_in[8];
    const float* bf = (const float*)d_in[9];
    const float* bi = (const float*)d_in[10];
    const float* bo = (const float*)d_in[11];
    const float* bc = (const float*)d_in[12];
    float* out = (float*)d_out;

    cudaFuncSetAttribute(lstm_persistent,
                         cudaFuncAttributeMaxDynamicSharedMemorySize, SMEM_BYTES);

    lstm_init_gates<<<dim3(H_SZ / 256, B_SZ / 8, 4), 256>>>(
        x, wf, wi, wo, wc, bf, bi, bo, bc);
    lstm_persistent<<<GRID, NTHR, SMEM_BYTES>>>(uf, ui, uo, uc, out);
}